// round 8
// baseline (speedup 1.0000x reference)
#include <cuda_runtime.h>
#include <cuda_fp16.h>
#include <cstdint>

// ---------------------------------------------------------------------------
// GraphConvolution: out = segment_sum( (X@W)[edge_src] * edge_val, edge_dst )
// Stage 0a: X f32 -> fp16 (g_Xh, padded to CTA grid)
// Stage 0b: W f32 [k][n] -> fp16 transposed [n][k]
// Stage 1: GEMM mma.sync fp16, cp.async 3-stage pipeline, BK=32
// Stage 2: rowptr via binary search (edge_dst sorted)
// Stage 3: warp-per-node segment sum, fp16 gathers, fp32 accum
// ---------------------------------------------------------------------------

#define MAX_NODES 50000
#define PAD_NODES 50048      // 391 CTAs * 128 rows
#define D_IN      512
#define D_OUT     128
#define BK        32
#define NSTEP     (D_IN / BK)   // 16
#define STAGES    3

__device__ __align__(16) __half g_support_h[(size_t)MAX_NODES * D_OUT];
__device__ int   g_rowptr[MAX_NODES + 1];
__device__ __align__(16) __half g_Wh[D_OUT * D_IN];            // [n][k]
__device__ __align__(16) __half g_Xh[(size_t)PAD_NODES * D_IN]; // [m][k]

// ------------------------------- helpers -----------------------------------
__device__ __forceinline__ uint32_t smem_u32(const void* p) {
    uint32_t a;
    asm("{ .reg .u64 t; cvta.to.shared.u64 t, %1; cvt.u32.u64 %0, t; }"
        : "=r"(a) : "l"(p));
    return a;
}
// 64B-row swizzle: 16B chunk index ^= (row>>1)&3  (conflict-free ldmatrix)
__device__ __forceinline__ uint32_t swz64(uint32_t r, uint32_t c) {
    return r * 64 + ((((c >> 4) ^ (r >> 1)) & 3u) << 4) + (c & 15u);
}

#define CP_ASYNC16(dst, src) \
    asm volatile("cp.async.cg.shared.global [%0], [%1], 16;" \
        :: "r"(dst), "l"(src) : "memory")
#define CP_COMMIT() asm volatile("cp.async.commit_group;" ::: "memory")
#define CP_WAIT1()  asm volatile("cp.async.wait_group 1;" ::: "memory")

#define LDSM4(r0, r1, r2, r3, a) \
    asm volatile("ldmatrix.sync.aligned.m8n8.x4.shared.b16 {%0,%1,%2,%3}, [%4];" \
        : "=r"(r0), "=r"(r1), "=r"(r2), "=r"(r3) : "r"(a))
#define LDSM2(r0, r1, a) \
    asm volatile("ldmatrix.sync.aligned.m8n8.x2.shared.b16 {%0,%1}, [%2];" \
        : "=r"(r0), "=r"(r1) : "r"(a))
#define MMA16816F16(c, a, b) \
    asm volatile("mma.sync.aligned.m16n8k16.row.col.f32.f16.f16.f32 " \
        "{%0,%1,%2,%3}, {%4,%5,%6,%7}, {%8,%9}, {%0,%1,%2,%3};" \
        : "+f"((c)[0]), "+f"((c)[1]), "+f"((c)[2]), "+f"((c)[3]) \
        : "r"((a)[0]), "r"((a)[1]), "r"((a)[2]), "r"((a)[3]), \
          "r"((b)[0]), "r"((b)[1]))

__device__ __forceinline__ uint32_t pack_h2(float lo, float hi) {
    __half2 h = __float22half2_rn(make_float2(lo, hi));
    return *reinterpret_cast<uint32_t*>(&h);
}

// ---------------------------------------------------------------------------
// Stage 0a: X f32 -> fp16 (zero-fill padding rows)
// ---------------------------------------------------------------------------
__global__ void convx_kernel(const float* __restrict__ X, int M)
{
    size_t i = ((size_t)blockIdx.x * blockDim.x + threadIdx.x) * 8;
    if (i >= (size_t)PAD_NODES * D_IN) return;
    int row = (int)(i >> 9);
    uint4 o;
    if (row < M) {
        float4 v0 = *reinterpret_cast<const float4*>(&X[i]);
        float4 v1 = *reinterpret_cast<const float4*>(&X[i + 4]);
        o = make_uint4(pack_h2(v0.x, v0.y), pack_h2(v0.z, v0.w),
                       pack_h2(v1.x, v1.y), pack_h2(v1.z, v1.w));
    } else {
        o = make_uint4(0u, 0u, 0u, 0u);
    }
    *reinterpret_cast<uint4*>(&g_Xh[i]) = o;
}

// ---------------------------------------------------------------------------
// Stage 0b: convert + transpose W -> fp16 [n][k]
// ---------------------------------------------------------------------------
__global__ void convw_kernel(const float* __restrict__ W)
{
    int idx = blockIdx.x * blockDim.x + threadIdx.x;
    if (idx >= D_IN * D_OUT) return;
    int k = idx >> 7;
    int n = idx & 127;
    g_Wh[n * D_IN + k] = __float2half_rn(W[idx]);
}

// ---------------------------------------------------------------------------
// Stage 1: GEMM, cp.async 3-stage, BK=32, 128x128 tile, 8 warps
// stage layout: A (128 rows x 64B) 8KB + B (128 rows x 64B) 8KB = 16KB
// ---------------------------------------------------------------------------
__global__ __launch_bounds__(256, 2)
void gemm_mma_kernel(int M)
{
    __shared__ __align__(128) char sm[STAGES][16384];

    const int tid  = threadIdx.x;
    const int w    = tid >> 5;
    const int lane = tid & 31;
    const int gid  = lane >> 2;
    const int tig  = lane & 3;
    const int rowBase = blockIdx.x * 128;
    const int mBase = (w >> 2) * 64;
    const int nBase = (w & 3) * 32;

    float acc[4][4][4];
#pragma unroll
    for (int i = 0; i < 4; i++)
#pragma unroll
        for (int j = 0; j < 4; j++)
#pragma unroll
            for (int q = 0; q < 4; q++) acc[i][j][q] = 0.f;

    // cp.async coords: thread -> row ar (0..127), byte-col base ac (0 or 32);
    // copies two 16B chunks per tile (bytes [ac,ac+16) and [ac+16,ac+32)).
    const int ar = tid >> 1;
    const int ac = (tid & 1) * 32;
    const uint32_t smBase = smem_u32(sm);
    const __half* xrow = &g_Xh[(size_t)(rowBase + ar) * D_IN];
    const __half* wrow = &g_Wh[(size_t)ar * D_IN];

    // byte col c within a 64B stage row -> global half offset k0 + c/2
    auto issue_stage = [&](int s, int k0) {
        uint32_t aBase = smBase + s * 16384;
        uint32_t bBase = aBase + 8192;
        uint32_t d0 = aBase + swz64((uint32_t)ar, (uint32_t)ac);
        uint32_t d1 = aBase + swz64((uint32_t)ar, (uint32_t)(ac + 16));
        CP_ASYNC16(d0, xrow + k0 + ac / 2);
        CP_ASYNC16(d1, xrow + k0 + ac / 2 + 8);
        uint32_t e0 = bBase + swz64((uint32_t)ar, (uint32_t)ac);
        uint32_t e1 = bBase + swz64((uint32_t)ar, (uint32_t)(ac + 16));
        CP_ASYNC16(e0, wrow + k0 + ac / 2);
        CP_ASYNC16(e1, wrow + k0 + ac / 2 + 8);
    };

    // prologue: stages 0 and 1
    issue_stage(0, 0);
    CP_COMMIT();
    issue_stage(1, BK);
    CP_COMMIT();

    int stage = 0;
    for (int i = 0; i < NSTEP; i++) {
        CP_WAIT1();
        __syncthreads();

        // issue stage i+2 (overlaps compute below)
        if (i + 2 < NSTEP) {
            int s2 = stage + 2; if (s2 >= STAGES) s2 -= STAGES;
            issue_stage(s2, (i + 2) * BK);
        }
        CP_COMMIT();

        const uint32_t aBase = smBase + stage * 16384;
        const uint32_t bBase = aBase + 8192;
#pragma unroll
        for (int s = 0; s < 2; s++) {       // two k16 sub-steps
            uint32_t af[4][4], bf[4][2];
#pragma unroll
            for (int mf = 0; mf < 4; mf++) {
                uint32_t a = aBase + swz64((uint32_t)(mBase + mf * 16 + (lane & 15)),
                                           (uint32_t)(s * 32 + ((lane >> 4) & 1) * 16));
                LDSM4(af[mf][0], af[mf][1], af[mf][2], af[mf][3], a);
            }
#pragma unroll
            for (int nf = 0; nf < 4; nf++) {
                uint32_t b = bBase + swz64((uint32_t)(nBase + nf * 8 + (lane & 7)),
                                           (uint32_t)(s * 32 + ((lane >> 3) & 1) * 16));
                LDSM2(bf[nf][0], bf[nf][1], b);
            }
#pragma unroll
            for (int mf = 0; mf < 4; mf++)
#pragma unroll
                for (int nf = 0; nf < 4; nf++)
                    MMA16816F16(acc[mf][nf], af[mf], bf[nf]);
        }
        __syncthreads();
        if (++stage == STAGES) stage = 0;
    }

    // ---- epilogue: write support as fp16 ----
#pragma unroll
    for (int mf = 0; mf < 4; mf++) {
        int r0 = rowBase + mBase + mf * 16 + gid;
        int r1 = r0 + 8;
#pragma unroll
        for (int nf = 0; nf < 4; nf++) {
            int col = nBase + nf * 8 + tig * 2;
            if (r0 < M)
                *reinterpret_cast<uint32_t*>(&g_support_h[(size_t)r0 * D_OUT + col]) =
                    pack_h2(acc[mf][nf][0], acc[mf][nf][1]);
            if (r1 < M)
                *reinterpret_cast<uint32_t*>(&g_support_h[(size_t)r1 * D_OUT + col]) =
                    pack_h2(acc[mf][nf][2], acc[mf][nf][3]);
        }
    }
}

// ---------------------------------------------------------------------------
// Stage 2: rowptr[i] = lower_bound(edge_dst, i)
// ---------------------------------------------------------------------------
__global__ void rowptr_kernel(const int* __restrict__ edge_dst, int E, int M)
{
    int i = blockIdx.x * blockDim.x + threadIdx.x;
    if (i > M) return;
    int lo = 0, hi = E;
    while (lo < hi) {
        int mid = (lo + hi) >> 1;
        if (edge_dst[mid] < i) lo = mid + 1; else hi = mid;
    }
    g_rowptr[i] = lo;
}

// ---------------------------------------------------------------------------
// Stage 3: warp per node segment sum; fp16 gathers (8B/lane), fp32 accum
// ---------------------------------------------------------------------------
__global__ __launch_bounds__(256)
void spmm_kernel(const int* __restrict__ edge_src,
                 const float* __restrict__ edge_val,
                 float* __restrict__ out, int M)
{
    const int warp = threadIdx.x >> 5;
    const int lane = threadIdx.x & 31;
    const int node = blockIdx.x * 8 + warp;
    if (node >= M) return;

    const int s = g_rowptr[node];
    const int e = g_rowptr[node + 1];

    float4 acc = make_float4(0.f, 0.f, 0.f, 0.f);
    float4 acc2 = make_float4(0.f, 0.f, 0.f, 0.f);
    const int col = lane * 4;
    const __half* supp = g_support_h;

    int i = s;
    for (; i + 3 < e; i += 4) {
        int s0 = edge_src[i + 0], s1 = edge_src[i + 1];
        int s2 = edge_src[i + 2], s3 = edge_src[i + 3];
        float v0 = edge_val[i + 0], v1 = edge_val[i + 1];
        float v2 = edge_val[i + 2], v3 = edge_val[i + 3];
        uint2 q0 = *reinterpret_cast<const uint2*>(&supp[(size_t)s0 * D_OUT + col]);
        uint2 q1 = *reinterpret_cast<const uint2*>(&supp[(size_t)s1 * D_OUT + col]);
        uint2 q2 = *reinterpret_cast<const uint2*>(&supp[(size_t)s2 * D_OUT + col]);
        uint2 q3 = *reinterpret_cast<const uint2*>(&supp[(size_t)s3 * D_OUT + col]);
        float2 a0 = __half22float2(*reinterpret_cast<__half2*>(&q0.x));
        float2 b0 = __half22float2(*reinterpret_cast<__half2*>(&q0.y));
        float2 a1 = __half22float2(*reinterpret_cast<__half2*>(&q1.x));
        float2 b1 = __half22float2(*reinterpret_cast<__half2*>(&q1.y));
        float2 a2 = __half22float2(*reinterpret_cast<__half2*>(&q2.x));
        float2 b2 = __half22float2(*reinterpret_cast<__half2*>(&q2.y));
        float2 a3 = __half22float2(*reinterpret_cast<__half2*>(&q3.x));
        float2 b3 = __half22float2(*reinterpret_cast<__half2*>(&q3.y));
        acc.x  = fmaf(a0.x, v0, acc.x);  acc.y  = fmaf(a0.y, v0, acc.y);
        acc.z  = fmaf(b0.x, v0, acc.z);  acc.w  = fmaf(b0.y, v0, acc.w);
        acc2.x = fmaf(a1.x, v1, acc2.x); acc2.y = fmaf(a1.y, v1, acc2.y);
        acc2.z = fmaf(b1.x, v1, acc2.z); acc2.w = fmaf(b1.y, v1, acc2.w);
        acc.x  = fmaf(a2.x, v2, acc.x);  acc.y  = fmaf(a2.y, v2, acc.y);
        acc.z  = fmaf(b2.x, v2, acc.z);  acc.w  = fmaf(b2.y, v2, acc.w);
        acc2.x = fmaf(a3.x, v3, acc2.x); acc2.y = fmaf(a3.y, v3, acc2.y);
        acc2.z = fmaf(b3.x, v3, acc2.z); acc2.w = fmaf(b3.y, v3, acc2.w);
    }
    for (; i < e; ++i) {
        int sr = edge_src[i];
        float v = edge_val[i];
        uint2 q = *reinterpret_cast<const uint2*>(&supp[(size_t)sr * D_OUT + col]);
        float2 f0 = __half22float2(*reinterpret_cast<__half2*>(&q.x));
        float2 f1 = __half22float2(*reinterpret_cast<__half2*>(&q.y));
        acc.x = fmaf(f0.x, v, acc.x); acc.y = fmaf(f0.y, v, acc.y);
        acc.z = fmaf(f1.x, v, acc.z); acc.w = fmaf(f1.y, v, acc.w);
    }
    acc.x += acc2.x; acc.y += acc2.y; acc.z += acc2.z; acc.w += acc2.w;

    *reinterpret_cast<float4*>(&out[(size_t)node * D_OUT + col]) = acc;
}

// ---------------------------------------------------------------------------
extern "C" void kernel_launch(void* const* d_in, const int* in_sizes, int n_in,
                              void* d_out, int out_size)
{
    const float* x        = (const float*)d_in[0];
    const int*   edge_src = (const int*)  d_in[1];
    const int*   edge_dst = (const int*)  d_in[2];
    const float* edge_val = (const float*)d_in[3];
    const float* weight   = (const float*)d_in[4];
    float*       out      = (float*)d_out;

    const int M = in_sizes[0] / D_IN;   // 50000
    const int E = in_sizes[1];          // 800000

    const int nconvx = (int)(((size_t)PAD_NODES * D_IN / 8 + 255) / 256);
    convx_kernel<<<nconvx, 256>>>(x, M);
    convw_kernel<<<(D_IN * D_OUT + 255) / 256, 256>>>(weight);
    rowptr_kernel<<<(M + 1 + 255) / 256, 256>>>(edge_dst, E, M);
    gemm_mma_kernel<<<(M + 127) / 128, 256>>>(M);
    spmm_kernel<<<(M + 7) / 8, 256>>>(edge_src, edge_val, out, M);
}

// round 9
// speedup vs baseline: 1.1766x; 1.1766x over previous
#include <cuda_runtime.h>
#include <cuda_fp16.h>
#include <cstdint>

// ---------------------------------------------------------------------------
// GraphConvolution: out = segment_sum( (X@W)[edge_src] * edge_val, edge_dst )
// Stage 0: W f32 [k][n] -> fp16 transposed [n][k]
// Stage 1: GEMM mma.sync fp16; cp.async pipeline carries RAW f32 X tiles,
//          converted to fp16 in-smem one stage ahead of the MMA (fused convx)
// Stage 2: rowptr via binary search (edge_dst sorted)
// Stage 3: warp-per-node segment sum, fp16 gathers, fp32 accum
// ---------------------------------------------------------------------------

#define MAX_NODES 50000
#define D_IN      512
#define D_OUT     128
#define BK        32
#define NSTEP     (D_IN / BK)   // 16
#define STAGES    3

// dynamic smem layout (bytes):
//   [0, 49152)        A f32 slots: 3 x 16384 (128 rows x 128B)
//   [49152, 73728)    B f16 slots: 3 x 8192  (128 rows x 64B)
//   [73728, 90112)    A f16 ping-pong: 2 x 8192
#define OFF_AF32  0
#define OFF_BF16  49152
#define OFF_AF16  73728
#define SMEM_DYN  90112

__device__ __align__(16) __half g_support_h[(size_t)MAX_NODES * D_OUT];
__device__ int   g_rowptr[MAX_NODES + 1];
__device__ __align__(16) __half g_Wh[D_OUT * D_IN];            // [n][k]

// ------------------------------- helpers -----------------------------------
__device__ __forceinline__ uint32_t smem_u32(const void* p) {
    uint32_t a;
    asm("{ .reg .u64 t; cvta.to.shared.u64 t, %1; cvt.u32.u64 %0, t; }"
        : "=r"(a) : "l"(p));
    return a;
}
// 64B-row swizzle (fp16 tiles): 16B chunk idx ^= (row>>1)&3
__device__ __forceinline__ uint32_t swz64(uint32_t r, uint32_t c) {
    return r * 64 + ((((c >> 4) ^ (r >> 1)) & 3u) << 4) + (c & 15u);
}
// 128B-row swizzle (f32 tiles): 16B chunk idx ^= row&7
__device__ __forceinline__ uint32_t swzf32(uint32_t r, uint32_t c) {
    return r * 128 + ((((c >> 4) ^ r) & 7u) << 4) + (c & 15u);
}

#define CP_ASYNC16(dst, src) \
    asm volatile("cp.async.cg.shared.global [%0], [%1], 16;" \
        :: "r"(dst), "l"(src) : "memory")
#define CP_COMMIT() asm volatile("cp.async.commit_group;" ::: "memory")
#define CP_WAIT1()  asm volatile("cp.async.wait_group 1;" ::: "memory")
#define CP_WAIT2()  asm volatile("cp.async.wait_group 2;" ::: "memory")

#define LDSM4(r0, r1, r2, r3, a) \
    asm volatile("ldmatrix.sync.aligned.m8n8.x4.shared.b16 {%0,%1,%2,%3}, [%4];" \
        : "=r"(r0), "=r"(r1), "=r"(r2), "=r"(r3) : "r"(a))
#define LDSM2(r0, r1, a) \
    asm volatile("ldmatrix.sync.aligned.m8n8.x2.shared.b16 {%0,%1}, [%2];" \
        : "=r"(r0), "=r"(r1) : "r"(a))
#define MMA16816F16(c, a, b) \
    asm volatile("mma.sync.aligned.m16n8k16.row.col.f32.f16.f16.f32 " \
        "{%0,%1,%2,%3}, {%4,%5,%6,%7}, {%8,%9}, {%0,%1,%2,%3};" \
        : "+f"((c)[0]), "+f"((c)[1]), "+f"((c)[2]), "+f"((c)[3]) \
        : "r"((a)[0]), "r"((a)[1]), "r"((a)[2]), "r"((a)[3]), \
          "r"((b)[0]), "r"((b)[1]))

__device__ __forceinline__ uint32_t pack_h2(float lo, float hi) {
    __half2 h = __float22half2_rn(make_float2(lo, hi));
    return *reinterpret_cast<uint32_t*>(&h);
}

// ---------------------------------------------------------------------------
// Stage 0: convert + transpose W -> fp16 [n][k]
// ---------------------------------------------------------------------------
__global__ void convw_kernel(const float* __restrict__ W)
{
    int idx = blockIdx.x * blockDim.x + threadIdx.x;
    if (idx >= D_IN * D_OUT) return;
    int k = idx >> 7;
    int n = idx & 127;
    g_Wh[n * D_IN + k] = __float2half_rn(W[idx]);
}

// ---------------------------------------------------------------------------
// Stage 1: GEMM, cp.async 3-stage (f32 A + f16 B), fused in-smem conversion
// ---------------------------------------------------------------------------
__global__ __launch_bounds__(256, 2)
void gemm_mma_kernel(const float* __restrict__ X, int M)
{
    extern __shared__ char dyn[];
    const uint32_t sb = smem_u32(dyn);

    const int tid  = threadIdx.x;
    const int w    = tid >> 5;
    const int lane = tid & 31;
    const int gid  = lane >> 2;
    const int tig  = lane & 3;
    const int rowBase = blockIdx.x * 128;
    const int mBase = (w >> 2) * 64;
    const int nBase = (w & 3) * 32;

    float acc[4][4][4];
#pragma unroll
    for (int i = 0; i < 4; i++)
#pragma unroll
        for (int j = 0; j < 4; j++)
#pragma unroll
            for (int q = 0; q < 4; q++) acc[i][j][q] = 0.f;

    // per-thread copy coords: row ar (0..127), f32 byte-seg aseg (0 or 64)
    const int ar   = tid >> 1;
    const int aseg = (tid & 1) * 64;
    const int bc   = (tid & 1) * 32;
    // OOB rows clamped to M-1 (their results are masked in the epilogue)
    const float*  xsrc = X + (size_t)(rowBase + ar < M ? rowBase + ar : M - 1) * D_IN;
    const __half* wsrc = g_Wh + (size_t)ar * D_IN;

    // copy stage s <- k chunk k0 (f32 A: 4 x 16B; f16 B: 2 x 16B)
    auto issue_stage = [&](int s, int k0) {
        uint32_t aB = sb + OFF_AF32 + s * 16384;
        uint32_t bB = sb + OFF_BF16 + s * 8192;
#pragma unroll
        for (int j = 0; j < 4; j++) {
            int c = aseg + j * 16;                      // byte col in 128B row
            CP_ASYNC16(aB + swzf32((uint32_t)ar, (uint32_t)c), xsrc + k0 + c / 4);
        }
        CP_ASYNC16(bB + swz64((uint32_t)ar, (uint32_t)bc),        wsrc + k0 + bc / 2);
        CP_ASYNC16(bB + swz64((uint32_t)ar, (uint32_t)(bc + 16)), wsrc + k0 + bc / 2 + 8);
    };

    // convert A f32 slot s -> fp16 ping-pong buffer p (16 floats/thread)
    auto convert_stage = [&](int s, int p) {
        const char* src = dyn + OFF_AF32 + s * 16384;
        char*       dst = dyn + OFF_AF16 + p * 8192;
        float4 f0 = *reinterpret_cast<const float4*>(src + swzf32((uint32_t)ar, (uint32_t)(aseg)));
        float4 f1 = *reinterpret_cast<const float4*>(src + swzf32((uint32_t)ar, (uint32_t)(aseg + 16)));
        float4 f2 = *reinterpret_cast<const float4*>(src + swzf32((uint32_t)ar, (uint32_t)(aseg + 32)));
        float4 f3 = *reinterpret_cast<const float4*>(src + swzf32((uint32_t)ar, (uint32_t)(aseg + 48)));
        uint4 h0 = make_uint4(pack_h2(f0.x, f0.y), pack_h2(f0.z, f0.w),
                              pack_h2(f1.x, f1.y), pack_h2(f1.z, f1.w));
        uint4 h1 = make_uint4(pack_h2(f2.x, f2.y), pack_h2(f2.z, f2.w),
                              pack_h2(f3.x, f3.y), pack_h2(f3.z, f3.w));
        *reinterpret_cast<uint4*>(dst + swz64((uint32_t)ar, (uint32_t)(aseg / 2)))      = h0;
        *reinterpret_cast<uint4*>(dst + swz64((uint32_t)ar, (uint32_t)(aseg / 2 + 16))) = h1;
    };

    // ---- prologue: stages 0,1,2 in flight; convert stage 0 ----
    issue_stage(0, 0);       CP_COMMIT();
    issue_stage(1, BK);      CP_COMMIT();
    issue_stage(2, 2 * BK);  CP_COMMIT();
    CP_WAIT2();              // stage 0 landed
    __syncthreads();
    convert_stage(0, 0);
    __syncthreads();

    for (int i = 0; i < NSTEP; i++) {
        const int cur = i % 3;
        const int pp  = i & 1;

        // make stage i+1 visible, convert it one step ahead of its MMA
        if (i + 1 < NSTEP) {
            CP_WAIT1();          // group arithmetic: one commit per iter below
            __syncthreads();
            convert_stage((i + 1) % 3, pp ^ 1);
        }

        // ---- MMA on Af16[pp] and B slot cur ----
        const uint32_t aBase = sb + OFF_AF16 + pp * 8192;
        const uint32_t bBase = sb + OFF_BF16 + cur * 8192;
#pragma unroll
        for (int s = 0; s < 2; s++) {       // two k16 sub-steps
            uint32_t af[4][4], bf[4][2];
#pragma unroll
            for (int mf = 0; mf < 4; mf++) {
                uint32_t a = aBase + swz64((uint32_t)(mBase + mf * 16 + (lane & 15)),
                                           (uint32_t)(s * 32 + ((lane >> 4) & 1) * 16));
                LDSM4(af[mf][0], af[mf][1], af[mf][2], af[mf][3], a);
            }
#pragma unroll
            for (int nf = 0; nf < 4; nf++) {
                uint32_t b = bBase + swz64((uint32_t)(nBase + nf * 8 + (lane & 7)),
                                           (uint32_t)(s * 32 + ((lane >> 3) & 1) * 16));
                LDSM2(bf[nf][0], bf[nf][1], b);
            }
#pragma unroll
            for (int mf = 0; mf < 4; mf++)
#pragma unroll
                for (int nf = 0; nf < 4; nf++)
                    MMA16816F16(acc[mf][nf], af[mf], bf[nf]);
        }
        __syncthreads();        // B slot cur + Af16[pp^1] free to reuse

        if (i + 3 < NSTEP)
            issue_stage(cur, (i + 3) * BK);
        CP_COMMIT();            // commit every iter (empty groups keep count uniform)
    }

    // ---- epilogue: write support as fp16 ----
#pragma unroll
    for (int mf = 0; mf < 4; mf++) {
        int r0 = rowBase + mBase + mf * 16 + gid;
        int r1 = r0 + 8;
#pragma unroll
        for (int nf = 0; nf < 4; nf++) {
            int col = nBase + nf * 8 + tig * 2;
            if (r0 < M)
                *reinterpret_cast<uint32_t*>(&g_support_h[(size_t)r0 * D_OUT + col]) =
                    pack_h2(acc[mf][nf][0], acc[mf][nf][1]);
            if (r1 < M)
                *reinterpret_cast<uint32_t*>(&g_support_h[(size_t)r1 * D_OUT + col]) =
                    pack_h2(acc[mf][nf][2], acc[mf][nf][3]);
        }
    }
}

// ---------------------------------------------------------------------------
// Stage 2: rowptr[i] = lower_bound(edge_dst, i)
// ---------------------------------------------------------------------------
__global__ void rowptr_kernel(const int* __restrict__ edge_dst, int E, int M)
{
    int i = blockIdx.x * blockDim.x + threadIdx.x;
    if (i > M) return;
    int lo = 0, hi = E;
    while (lo < hi) {
        int mid = (lo + hi) >> 1;
        if (edge_dst[mid] < i) lo = mid + 1; else hi = mid;
    }
    g_rowptr[i] = lo;
}

// ---------------------------------------------------------------------------
// Stage 3: warp per node segment sum; fp16 gathers (8B/lane), fp32 accum
// ---------------------------------------------------------------------------
__global__ __launch_bounds__(256)
void spmm_kernel(const int* __restrict__ edge_src,
                 const float* __restrict__ edge_val,
                 float* __restrict__ out, int M)
{
    const int warp = threadIdx.x >> 5;
    const int lane = threadIdx.x & 31;
    const int node = blockIdx.x * 8 + warp;
    if (node >= M) return;

    const int s = g_rowptr[node];
    const int e = g_rowptr[node + 1];

    float4 acc = make_float4(0.f, 0.f, 0.f, 0.f);
    float4 acc2 = make_float4(0.f, 0.f, 0.f, 0.f);
    const int col = lane * 4;
    const __half* supp = g_support_h;

    int i = s;
    for (; i + 3 < e; i += 4) {
        int s0 = edge_src[i + 0], s1 = edge_src[i + 1];
        int s2 = edge_src[i + 2], s3 = edge_src[i + 3];
        float v0 = edge_val[i + 0], v1 = edge_val[i + 1];
        float v2 = edge_val[i + 2], v3 = edge_val[i + 3];
        uint2 q0 = *reinterpret_cast<const uint2*>(&supp[(size_t)s0 * D_OUT + col]);
        uint2 q1 = *reinterpret_cast<const uint2*>(&supp[(size_t)s1 * D_OUT + col]);
        uint2 q2 = *reinterpret_cast<const uint2*>(&supp[(size_t)s2 * D_OUT + col]);
        uint2 q3 = *reinterpret_cast<const uint2*>(&supp[(size_t)s3 * D_OUT + col]);
        float2 a0 = __half22float2(*reinterpret_cast<__half2*>(&q0.x));
        float2 b0 = __half22float2(*reinterpret_cast<__half2*>(&q0.y));
        float2 a1 = __half22float2(*reinterpret_cast<__half2*>(&q1.x));
        float2 b1 = __half22float2(*reinterpret_cast<__half2*>(&q1.y));
        float2 a2 = __half22float2(*reinterpret_cast<__half2*>(&q2.x));
        float2 b2 = __half22float2(*reinterpret_cast<__half2*>(&q2.y));
        float2 a3 = __half22float2(*reinterpret_cast<__half2*>(&q3.x));
        float2 b3 = __half22float2(*reinterpret_cast<__half2*>(&q3.y));
        acc.x  = fmaf(a0.x, v0, acc.x);  acc.y  = fmaf(a0.y, v0, acc.y);
        acc.z  = fmaf(b0.x, v0, acc.z);  acc.w  = fmaf(b0.y, v0, acc.w);
        acc2.x = fmaf(a1.x, v1, acc2.x); acc2.y = fmaf(a1.y, v1, acc2.y);
        acc2.z = fmaf(b1.x, v1, acc2.z); acc2.w = fmaf(b1.y, v1, acc2.w);
        acc.x  = fmaf(a2.x, v2, acc.x);  acc.y  = fmaf(a2.y, v2, acc.y);
        acc.z  = fmaf(b2.x, v2, acc.z);  acc.w  = fmaf(b2.y, v2, acc.w);
        acc2.x = fmaf(a3.x, v3, acc2.x); acc2.y = fmaf(a3.y, v3, acc2.y);
        acc2.z = fmaf(b3.x, v3, acc2.z); acc2.w = fmaf(b3.y, v3, acc2.w);
    }
    for (; i < e; ++i) {
        int sr = edge_src[i];
        float v = edge_val[i];
        uint2 q = *reinterpret_cast<const uint2*>(&supp[(size_t)sr * D_OUT + col]);
        float2 f0 = __half22float2(*reinterpret_cast<__half2*>(&q.x));
        float2 f1 = __half22float2(*reinterpret_cast<__half2*>(&q.y));
        acc.x = fmaf(f0.x, v, acc.x); acc.y = fmaf(f0.y, v, acc.y);
        acc.z = fmaf(f1.x, v, acc.z); acc.w = fmaf(f1.y, v, acc.w);
    }
    acc.x += acc2.x; acc.y += acc2.y; acc.z += acc2.z; acc.w += acc2.w;

    *reinterpret_cast<float4*>(&out[(size_t)node * D_OUT + col]) = acc;
}

// ---------------------------------------------------------------------------
extern "C" void kernel_launch(void* const* d_in, const int* in_sizes, int n_in,
                              void* d_out, int out_size)
{
    const float* x        = (const float*)d_in[0];
    const int*   edge_src = (const int*)  d_in[1];
    const int*   edge_dst = (const int*)  d_in[2];
    const float* edge_val = (const float*)d_in[3];
    const float* weight   = (const float*)d_in[4];
    float*       out      = (float*)d_out;

    const int M = in_sizes[0] / D_IN;   // 50000
    const int E = in_sizes[1];          // 800000

    cudaFuncSetAttribute(gemm_mma_kernel,
                         cudaFuncAttributeMaxDynamicSharedMemorySize, SMEM_DYN);

    convw_kernel<<<(D_IN * D_OUT + 255) / 256, 256>>>(weight);
    rowptr_kernel<<<(M + 1 + 255) / 256, 256>>>(edge_dst, E, M);
    gemm_mma_kernel<<<(M + 127) / 128, 256, SMEM_DYN>>>(x, M);
    spmm_kernel<<<(M + 7) / 8, 256>>>(edge_src, edge_val, out, M);
}